// round 1
// baseline (speedup 1.0000x reference)
#include <cuda_runtime.h>
#include <cuda_bf16.h>
#include <math.h>

#define N_NODES 50000
#define N_EDGES 800000
#define DIM 128
#define HEADS 4
#define OUTF 32
#define NEG_SLOPE 0.2f

// ---------------- scratch (static device globals; no allocation) ----------------
__device__ int   g_counts[N_NODES];
__device__ int   g_rowptr[N_NODES + 1];
__device__ int   g_cursor[N_NODES];
__device__ int   g_colsrc[N_EDGES];
__device__ int   g_coleid[N_EDGES];
__device__ float g_ft[N_NODES * DIM];
__device__ float g_h[N_NODES * DIM];
__device__ float g_el[N_NODES * HEADS];
__device__ float g_er[N_NODES * HEADS];

// ---------------- CSR build ----------------
__global__ void zero_counts_kernel() {
    int i = blockIdx.x * blockDim.x + threadIdx.x;
    if (i < N_NODES) g_counts[i] = 0;
}

__global__ void hist_kernel(const int* __restrict__ dst) {
    int e = blockIdx.x * blockDim.x + threadIdx.x;
    if (e < N_EDGES) atomicAdd(&g_counts[dst[e]], 1);
}

// single-block exclusive scan over g_counts -> g_rowptr (and g_cursor copy)
__global__ void scan_kernel() {
    __shared__ int smem[1024];
    __shared__ int s_carry;
    int tid = threadIdx.x;
    if (tid == 0) s_carry = 0;
    __syncthreads();
    for (int base = 0; base < N_NODES; base += 1024) {
        int i = base + tid;
        int v = (i < N_NODES) ? g_counts[i] : 0;
        smem[tid] = v;
        __syncthreads();
        #pragma unroll
        for (int off = 1; off < 1024; off <<= 1) {
            int t = (tid >= off) ? smem[tid - off] : 0;
            __syncthreads();
            smem[tid] += t;
            __syncthreads();
        }
        int excl = smem[tid] - v + s_carry;
        if (i < N_NODES) { g_rowptr[i] = excl; g_cursor[i] = excl; }
        __syncthreads();
        if (tid == 1023) s_carry += smem[1023];
        __syncthreads();
    }
    if (tid == 0) g_rowptr[N_NODES] = s_carry;
}

__global__ void scatter_kernel(const int* __restrict__ src, const int* __restrict__ dst) {
    int e = blockIdx.x * blockDim.x + threadIdx.x;
    if (e >= N_EDGES) return;
    int d = dst[e];
    int pos = atomicAdd(&g_cursor[d], 1);
    g_colsrc[pos] = src[e];
    g_coleid[pos] = e;
}

// ---------------- GEMM: C[M x 128] = A[M x 128] * W[128 x 128] (row-major) ----------------
__global__ void gemm128_kernel(const float* __restrict__ A, const float* __restrict__ W,
                               float* __restrict__ C, int M) {
    __shared__ float Ws[32][128];
    __shared__ float As[32][33];
    int block_row = blockIdx.x * 32;
    int tid = threadIdx.x;          // 256 threads
    int tx = tid & 31;              // col group (0..31) -> cols tx*4..tx*4+3
    int ty = tid >> 5;              // row group (0..7)  -> rows ty*4..ty*4+3
    float acc[4][4];
    #pragma unroll
    for (int i = 0; i < 4; i++)
        #pragma unroll
        for (int j = 0; j < 4; j++) acc[i][j] = 0.f;

    for (int k0 = 0; k0 < 128; k0 += 32) {
        // load W tile 32x128
        #pragma unroll
        for (int t = tid; t < 32 * 128; t += 256) {
            int r = t >> 7, c = t & 127;
            Ws[r][c] = W[(k0 + r) * 128 + c];
        }
        // load A tile 32x32
        #pragma unroll
        for (int t = tid; t < 32 * 32; t += 256) {
            int r = t >> 5, c = t & 31;
            int gr = block_row + r;
            As[r][c] = (gr < M) ? A[gr * 128 + k0 + c] : 0.f;
        }
        __syncthreads();
        #pragma unroll
        for (int k = 0; k < 32; k++) {
            float a0 = As[ty * 4 + 0][k];
            float a1 = As[ty * 4 + 1][k];
            float a2 = As[ty * 4 + 2][k];
            float a3 = As[ty * 4 + 3][k];
            float4 b = *reinterpret_cast<const float4*>(&Ws[k][tx * 4]);
            acc[0][0] += a0 * b.x; acc[0][1] += a0 * b.y; acc[0][2] += a0 * b.z; acc[0][3] += a0 * b.w;
            acc[1][0] += a1 * b.x; acc[1][1] += a1 * b.y; acc[1][2] += a1 * b.z; acc[1][3] += a1 * b.w;
            acc[2][0] += a2 * b.x; acc[2][1] += a2 * b.y; acc[2][2] += a2 * b.z; acc[2][3] += a2 * b.w;
            acc[3][0] += a3 * b.x; acc[3][1] += a3 * b.y; acc[3][2] += a3 * b.z; acc[3][3] += a3 * b.w;
        }
        __syncthreads();
    }
    #pragma unroll
    for (int i = 0; i < 4; i++) {
        int gr = block_row + ty * 4 + i;
        if (gr < M) {
            float4 v = make_float4(acc[i][0], acc[i][1], acc[i][2], acc[i][3]);
            *reinterpret_cast<float4*>(&C[gr * 128 + tx * 4]) = v;
        }
    }
}

// ---------------- el/er: per-(node,head) dot of 32 ----------------
__global__ void elr_kernel(const float* __restrict__ ft,
                           const float* __restrict__ al, const float* __restrict__ ar,
                           float* __restrict__ el, float* __restrict__ er) {
    int warp = (blockIdx.x * blockDim.x + threadIdx.x) >> 5;
    int lane = threadIdx.x & 31;
    if (warp >= N_NODES) return;
    const float* f = ft + warp * DIM;
    #pragma unroll
    for (int h = 0; h < 4; h++) {
        float x = f[h * 32 + lane];
        float sl = x * al[h * 32 + lane];
        float sr = x * ar[h * 32 + lane];
        #pragma unroll
        for (int off = 16; off > 0; off >>= 1) {
            sl += __shfl_xor_sync(0xffffffffu, sl, off);
            sr += __shfl_xor_sync(0xffffffffu, sr, off);
        }
        if (lane == 0) {
            el[warp * 4 + h] = sl;
            er[warp * 4 + h] = sr;
        }
    }
}

__device__ __forceinline__ float leaky(float v) {
    return v > 0.f ? v : NEG_SLOPE * v;
}

// ---------------- aggregation: warp per dst node, lane = feature ----------------
template <bool LAYER1>
__global__ void aggregate_kernel(const float* __restrict__ ft,
                                 const float* __restrict__ el, const float* __restrict__ er,
                                 const float* __restrict__ ew, const float* __restrict__ bias,
                                 float* __restrict__ out) {
    int i = (blockIdx.x * blockDim.x + threadIdx.x) >> 5;
    int lane = threadIdx.x & 31;
    if (i >= N_NODES) return;

    int beg = g_rowptr[i], end = g_rowptr[i + 1];
    float er0 = er[i * 4 + 0], er1 = er[i * 4 + 1], er2 = er[i * 4 + 2], er3 = er[i * 4 + 3];

    // pass 1: per-head max (lanes stride over edges)
    float m0 = -1e30f, m1 = -1e30f, m2 = -1e30f, m3 = -1e30f;
    for (int e = beg + lane; e < end; e += 32) {
        int s = g_colsrc[e];
        float4 lv = *reinterpret_cast<const float4*>(el + s * 4);
        m0 = fmaxf(m0, leaky(lv.x + er0));
        m1 = fmaxf(m1, leaky(lv.y + er1));
        m2 = fmaxf(m2, leaky(lv.z + er2));
        m3 = fmaxf(m3, leaky(lv.w + er3));
    }
    #pragma unroll
    for (int off = 16; off > 0; off >>= 1) {
        m0 = fmaxf(m0, __shfl_xor_sync(0xffffffffu, m0, off));
        m1 = fmaxf(m1, __shfl_xor_sync(0xffffffffu, m1, off));
        m2 = fmaxf(m2, __shfl_xor_sync(0xffffffffu, m2, off));
        m3 = fmaxf(m3, __shfl_xor_sync(0xffffffffu, m3, off));
    }

    // pass 2: lanes walk edges together, lane = feature within each head
    float acc0 = 0.f, acc1 = 0.f, acc2 = 0.f, acc3 = 0.f;
    float d0 = 0.f, d1 = 0.f, d2 = 0.f, d3 = 0.f;
    for (int e = beg; e < end; e++) {
        int s = g_colsrc[e];
        float w = ew[g_coleid[e]];
        float4 lv = *reinterpret_cast<const float4*>(el + s * 4);
        float x0 = __expf(leaky(lv.x + er0) - m0);
        float x1 = __expf(leaky(lv.y + er1) - m1);
        float x2 = __expf(leaky(lv.z + er2) - m2);
        float x3 = __expf(leaky(lv.w + er3) - m3);
        d0 += x0; d1 += x1; d2 += x2; d3 += x3;
        const float* f = ft + s * DIM;
        acc0 += x0 * w * f[lane];
        acc1 += x1 * w * f[32 + lane];
        acc2 += x2 * w * f[64 + lane];
        acc3 += x3 * w * f[96 + lane];
    }
    d0 = fmaxf(d0, 1e-9f); d1 = fmaxf(d1, 1e-9f);
    d2 = fmaxf(d2, 1e-9f); d3 = fmaxf(d3, 1e-9f);

    float v0 = acc0 / d0 + bias[lane];
    float v1 = acc1 / d1 + bias[32 + lane];
    float v2 = acc2 / d2 + bias[64 + lane];
    float v3 = acc3 / d3 + bias[96 + lane];

    if (!LAYER1) {
        out[i * 128 + lane]      = fmaxf(v0, 0.f);
        out[i * 128 + 32 + lane] = fmaxf(v1, 0.f);
        out[i * 128 + 64 + lane] = fmaxf(v2, 0.f);
        out[i * 128 + 96 + lane] = fmaxf(v3, 0.f);
    } else {
        out[i * 32 + lane] = 0.25f * (v0 + v1 + v2 + v3);
    }
}

// ---------------- launch ----------------
extern "C" void kernel_launch(void* const* d_in, const int* in_sizes, int n_in,
                              void* d_out, int out_size) {
    const float *x_am, *x_ph, *exist, *am_exist;
    const int *src, *dst;
    const float *W0a, *al0a, *ar0a, *b0a, *W0p, *al0p, *ar0p, *b0p;
    const float *W1a, *al1a, *ar1a, *b1a, *W1p, *al1p, *ar1p, *b1p;

    x_am = (const float*)d_in[0];
    x_ph = (const float*)d_in[1];
    exist = (const float*)d_in[2];
    am_exist = (const float*)d_in[3];

    if (in_sizes[4] == N_EDGES) {
        // setup_inputs dict order: src, dst in middle
        src = (const int*)d_in[4];
        dst = (const int*)d_in[5];
        W0a = (const float*)d_in[6];  al0a = (const float*)d_in[7];
        ar0a = (const float*)d_in[8]; b0a = (const float*)d_in[9];
        W0p = (const float*)d_in[10]; al0p = (const float*)d_in[11];
        ar0p = (const float*)d_in[12]; b0p = (const float*)d_in[13];
        W1a = (const float*)d_in[14]; al1a = (const float*)d_in[15];
        ar1a = (const float*)d_in[16]; b1a = (const float*)d_in[17];
        W1p = (const float*)d_in[18]; al1p = (const float*)d_in[19];
        ar1p = (const float*)d_in[20]; b1p = (const float*)d_in[21];
    } else {
        // reference() signature order: weights first, src/dst last
        W0a = (const float*)d_in[4];  al0a = (const float*)d_in[5];
        ar0a = (const float*)d_in[6]; b0a = (const float*)d_in[7];
        W0p = (const float*)d_in[8];  al0p = (const float*)d_in[9];
        ar0p = (const float*)d_in[10]; b0p = (const float*)d_in[11];
        W1a = (const float*)d_in[12]; al1a = (const float*)d_in[13];
        ar1a = (const float*)d_in[14]; b1a = (const float*)d_in[15];
        W1p = (const float*)d_in[16]; al1p = (const float*)d_in[17];
        ar1p = (const float*)d_in[18]; b1p = (const float*)d_in[19];
        src = (const int*)d_in[20];
        dst = (const int*)d_in[21];
    }

    float* out = (float*)d_out;

    // resolve device-global scratch pointers (host API, not stream ops: fine under capture)
    float *p_ft, *p_h, *p_el, *p_er;
    cudaGetSymbolAddress((void**)&p_ft, g_ft);
    cudaGetSymbolAddress((void**)&p_h, g_h);
    cudaGetSymbolAddress((void**)&p_el, g_el);
    cudaGetSymbolAddress((void**)&p_er, g_er);

    const int TB = 256;
    int gb_nodes = (N_NODES + TB - 1) / TB;
    int gb_edges = (N_EDGES + TB - 1) / TB;
    int gb_warp_nodes = (N_NODES * 32 + TB - 1) / TB;   // warp per node

    // CSR build (shared by all 4 convs)
    zero_counts_kernel<<<gb_nodes, TB>>>();
    hist_kernel<<<gb_edges, TB>>>(dst);
    scan_kernel<<<1, 1024>>>();
    scatter_kernel<<<gb_edges, TB>>>(src, dst);

    int gemm_blocks = (N_NODES + 31) / 32;

    for (int br = 0; br < 2; br++) {
        const float* x  = br ? x_ph : x_am;
        const float* ew = br ? exist : am_exist;
        const float* W0 = br ? W0p : W0a;
        const float* al0 = br ? al0p : al0a;
        const float* ar0 = br ? ar0p : ar0a;
        const float* b0 = br ? b0p : b0a;
        const float* W1 = br ? W1p : W1a;
        const float* al1 = br ? al1p : al1a;
        const float* ar1 = br ? ar1p : ar1a;
        const float* b1 = br ? b1p : b1a;
        float* out_br = out + (size_t)br * N_NODES * OUTF;

        // layer 0
        gemm128_kernel<<<gemm_blocks, 256>>>(x, W0, p_ft, N_NODES);
        elr_kernel<<<gb_warp_nodes, TB>>>(p_ft, al0, ar0, p_el, p_er);
        aggregate_kernel<false><<<gb_warp_nodes, TB>>>(p_ft, p_el, p_er, ew, b0, p_h);

        // layer 1
        gemm128_kernel<<<gemm_blocks, 256>>>(p_h, W1, p_ft, N_NODES);
        elr_kernel<<<gb_warp_nodes, TB>>>(p_ft, al1, ar1, p_el, p_er);
        aggregate_kernel<true><<<gb_warp_nodes, TB>>>(p_ft, p_el, p_er, ew, b1, out_br);
    }
}

// round 2
// speedup vs baseline: 1.6919x; 1.6919x over previous
#include <cuda_runtime.h>
#include <cuda_bf16.h>
#include <math.h>

#define N_NODES 50000
#define N_EDGES 800000
#define DIM 128
#define HEADS 4
#define OUTF 32
#define NEG_SLOPE 0.2f

#define SCAN_B 1024
#define SCAN_NB ((N_NODES + SCAN_B - 1) / SCAN_B)   // 49

// ---------------- scratch (static device globals; no allocation) ----------------
__device__ int   g_counts[N_NODES];
__device__ int   g_rowptr[N_NODES + 1];
__device__ int   g_cursor[N_NODES];
__device__ int   g_colsrc[N_EDGES];
__device__ float g_w_am[N_EDGES];
__device__ float g_w_ph[N_EDGES];
__device__ float g_alpha[N_EDGES * HEADS];
__device__ float g_denom[N_NODES * HEADS];
__device__ float g_ft[N_NODES * DIM];
__device__ float g_h[N_NODES * DIM];
__device__ float g_el[N_NODES * HEADS];
__device__ float g_er[N_NODES * HEADS];
__device__ int   g_bsum[SCAN_NB];
__device__ int   g_bsumex[SCAN_NB];

// ---------------- CSR build ----------------
__global__ void zero_counts_kernel() {
    int i = blockIdx.x * blockDim.x + threadIdx.x;
    if (i < N_NODES) g_counts[i] = 0;
}

__global__ void hist_kernel(const int* __restrict__ dst) {
    int e = blockIdx.x * blockDim.x + threadIdx.x;
    if (e < N_EDGES) atomicAdd(&g_counts[dst[e]], 1);
}

// partial sums: one block per 1024 counts
__global__ void scan_partial_kernel() {
    __shared__ int smem[256];
    int b = blockIdx.x, t = threadIdx.x;
    int base = b * SCAN_B;
    int s = 0;
    #pragma unroll
    for (int j = 0; j < 4; j++) {
        int i = base + t + j * 256;
        if (i < N_NODES) s += g_counts[i];
    }
    smem[t] = s;
    __syncthreads();
    for (int off = 128; off > 0; off >>= 1) {
        if (t < off) smem[t] += smem[t + off];
        __syncthreads();
    }
    if (t == 0) g_bsum[b] = smem[0];
}

// exclusive scan of the 49 block sums (single tiny block)
__global__ void scan_bsum_kernel() {
    __shared__ int smem[64];
    int t = threadIdx.x;
    int v = (t < SCAN_NB) ? g_bsum[t] : 0;
    smem[t] = v;
    __syncthreads();
    #pragma unroll
    for (int off = 1; off < 64; off <<= 1) {
        int x = (t >= off) ? smem[t - off] : 0;
        __syncthreads();
        smem[t] += x;
        __syncthreads();
    }
    if (t < SCAN_NB) g_bsumex[t] = smem[t] - v;
}

// per-block scan + offset, writes rowptr & cursor
__global__ void scan_write_kernel() {
    __shared__ int smem[SCAN_B];
    int b = blockIdx.x, t = threadIdx.x;
    int i = b * SCAN_B + t;
    int v = (i < N_NODES) ? g_counts[i] : 0;
    smem[t] = v;
    __syncthreads();
    #pragma unroll
    for (int off = 1; off < SCAN_B; off <<= 1) {
        int x = (t >= off) ? smem[t - off] : 0;
        __syncthreads();
        smem[t] += x;
        __syncthreads();
    }
    int excl = smem[t] - v + g_bsumex[b];
    if (i < N_NODES) {
        g_rowptr[i] = excl;
        g_cursor[i] = excl;
        if (i == N_NODES - 1) g_rowptr[N_NODES] = excl + v;
    }
}

__global__ void scatter_kernel(const int* __restrict__ src, const int* __restrict__ dst,
                               const float* __restrict__ am_w, const float* __restrict__ ph_w) {
    int e = blockIdx.x * blockDim.x + threadIdx.x;
    if (e >= N_EDGES) return;
    int d = dst[e];
    int pos = atomicAdd(&g_cursor[d], 1);
    g_colsrc[pos] = src[e];
    g_w_am[pos] = am_w[e];
    g_w_ph[pos] = ph_w[e];
}

// ---------------- GEMM: C[M x 128] = A[M x 128] * W[128 x 128] ----------------
// 64x128 block tile, 256 threads, 8x4 micro-tile
__global__ void gemm128_kernel(const float* __restrict__ A, const float* __restrict__ W,
                               float* __restrict__ C, int M) {
    __shared__ float As[16][68];   // transposed: As[k][row]
    __shared__ float Ws[16][128];
    int tid = threadIdx.x;
    int tx = tid & 31;             // col group -> cols tx*4..+3
    int ty = tid >> 5;             // row group -> rows ty*8..+7
    int br = blockIdx.x * 64;

    float acc[8][4];
    #pragma unroll
    for (int i = 0; i < 8; i++)
        #pragma unroll
        for (int j = 0; j < 4; j++) acc[i][j] = 0.f;

    for (int k0 = 0; k0 < 128; k0 += 16) {
        // A tile 64x16 -> transposed smem
        {
            int t = tid * 4;
            int r = t >> 4;         // 0..63
            int c = t & 15;         // 0,4,8,12
            float4 v = make_float4(0.f, 0.f, 0.f, 0.f);
            if (br + r < M) v = *reinterpret_cast<const float4*>(&A[(size_t)(br + r) * 128 + k0 + c]);
            As[c + 0][r] = v.x; As[c + 1][r] = v.y; As[c + 2][r] = v.z; As[c + 3][r] = v.w;
        }
        // W tile 16x128
        {
            int row = tid >> 4;       // 0..15
            int col = (tid & 15) * 8; // 0..120
            float4 v0 = *reinterpret_cast<const float4*>(&W[(k0 + row) * 128 + col]);
            float4 v1 = *reinterpret_cast<const float4*>(&W[(k0 + row) * 128 + col + 4]);
            *reinterpret_cast<float4*>(&Ws[row][col]) = v0;
            *reinterpret_cast<float4*>(&Ws[row][col + 4]) = v1;
        }
        __syncthreads();
        #pragma unroll
        for (int k = 0; k < 16; k++) {
            float4 alo = *reinterpret_cast<const float4*>(&As[k][ty * 8]);
            float4 ahi = *reinterpret_cast<const float4*>(&As[k][ty * 8 + 4]);
            float4 b = *reinterpret_cast<const float4*>(&Ws[k][tx * 4]);
            float a[8] = {alo.x, alo.y, alo.z, alo.w, ahi.x, ahi.y, ahi.z, ahi.w};
            #pragma unroll
            for (int i = 0; i < 8; i++) {
                acc[i][0] += a[i] * b.x;
                acc[i][1] += a[i] * b.y;
                acc[i][2] += a[i] * b.z;
                acc[i][3] += a[i] * b.w;
            }
        }
        __syncthreads();
    }
    #pragma unroll
    for (int i = 0; i < 8; i++) {
        int gr = br + ty * 8 + i;
        if (gr < M) {
            float4 v = make_float4(acc[i][0], acc[i][1], acc[i][2], acc[i][3]);
            *reinterpret_cast<float4*>(&C[(size_t)gr * 128 + tx * 4]) = v;
        }
    }
}

// ---------------- el/er: warp per node, float4 + 8-lane segmented reduce ----------------
__global__ void elr_kernel(const float* __restrict__ ft,
                           const float* __restrict__ al, const float* __restrict__ ar,
                           float* __restrict__ el, float* __restrict__ er) {
    int i = (blockIdx.x * blockDim.x + threadIdx.x) >> 5;
    int lane = threadIdx.x & 31;
    if (i >= N_NODES) return;
    float4 f = *reinterpret_cast<const float4*>(ft + (size_t)i * DIM + lane * 4);
    float4 a = *reinterpret_cast<const float4*>(al + lane * 4);
    float4 r = *reinterpret_cast<const float4*>(ar + lane * 4);
    float sl = f.x * a.x + f.y * a.y + f.z * a.z + f.w * a.w;
    float sr = f.x * r.x + f.y * r.y + f.z * r.z + f.w * r.w;
    #pragma unroll
    for (int off = 1; off < 8; off <<= 1) {
        sl += __shfl_xor_sync(0xffffffffu, sl, off);
        sr += __shfl_xor_sync(0xffffffffu, sr, off);
    }
    if ((lane & 7) == 0) {
        int h = lane >> 3;
        el[i * 4 + h] = sl;
        er[i * 4 + h] = sr;
    }
}

__device__ __forceinline__ float leaky(float v) {
    return v > 0.f ? v : NEG_SLOPE * v;
}

// ---------------- alpha: warp per node, lanes stride edges (lane-parallel exp) ----------------
__global__ void alpha_kernel(const float* __restrict__ el, const float* __restrict__ er,
                             const float* __restrict__ w) {
    int i = (blockIdx.x * blockDim.x + threadIdx.x) >> 5;
    int lane = threadIdx.x & 31;
    if (i >= N_NODES) return;
    int beg = g_rowptr[i], end = g_rowptr[i + 1];
    float4 e4 = *reinterpret_cast<const float4*>(er + i * 4);

    // pass 1: per-head max
    float m0 = -1e30f, m1 = -1e30f, m2 = -1e30f, m3 = -1e30f;
    for (int e = beg + lane; e < end; e += 32) {
        int s = g_colsrc[e];
        float4 lv = *reinterpret_cast<const float4*>(el + s * 4);
        m0 = fmaxf(m0, leaky(lv.x + e4.x));
        m1 = fmaxf(m1, leaky(lv.y + e4.y));
        m2 = fmaxf(m2, leaky(lv.z + e4.z));
        m3 = fmaxf(m3, leaky(lv.w + e4.w));
    }
    #pragma unroll
    for (int off = 16; off > 0; off >>= 1) {
        m0 = fmaxf(m0, __shfl_xor_sync(0xffffffffu, m0, off));
        m1 = fmaxf(m1, __shfl_xor_sync(0xffffffffu, m1, off));
        m2 = fmaxf(m2, __shfl_xor_sync(0xffffffffu, m2, off));
        m3 = fmaxf(m3, __shfl_xor_sync(0xffffffffu, m3, off));
    }

    // pass 2: exp + denom + store alpha (lane-parallel, coalesced)
    float d0 = 0.f, d1 = 0.f, d2 = 0.f, d3 = 0.f;
    for (int e = beg + lane; e < end; e += 32) {
        int s = g_colsrc[e];
        float we = w[e];
        float4 lv = *reinterpret_cast<const float4*>(el + s * 4);
        float x0 = __expf(leaky(lv.x + e4.x) - m0);
        float x1 = __expf(leaky(lv.y + e4.y) - m1);
        float x2 = __expf(leaky(lv.z + e4.z) - m2);
        float x3 = __expf(leaky(lv.w + e4.w) - m3);
        d0 += x0; d1 += x1; d2 += x2; d3 += x3;
        float4 av = make_float4(x0 * we, x1 * we, x2 * we, x3 * we);
        *reinterpret_cast<float4*>(g_alpha + (size_t)e * 4) = av;
    }
    #pragma unroll
    for (int off = 16; off > 0; off >>= 1) {
        d0 += __shfl_xor_sync(0xffffffffu, d0, off);
        d1 += __shfl_xor_sync(0xffffffffu, d1, off);
        d2 += __shfl_xor_sync(0xffffffffu, d2, off);
        d3 += __shfl_xor_sync(0xffffffffu, d3, off);
    }
    if (lane == 0) {
        float4 dv = make_float4(fmaxf(d0, 1e-9f), fmaxf(d1, 1e-9f),
                                fmaxf(d2, 1e-9f), fmaxf(d3, 1e-9f));
        *reinterpret_cast<float4*>(g_denom + i * 4) = dv;
    }
}

// ---------------- aggregation: warp per node, lane = feature ----------------
template <bool LAYER1>
__global__ void aggregate_kernel(const float* __restrict__ ft,
                                 const float* __restrict__ bias,
                                 float* __restrict__ out) {
    int i = (blockIdx.x * blockDim.x + threadIdx.x) >> 5;
    int lane = threadIdx.x & 31;
    if (i >= N_NODES) return;
    int beg = g_rowptr[i], end = g_rowptr[i + 1];

    float acc0 = 0.f, acc1 = 0.f, acc2 = 0.f, acc3 = 0.f;
    int e = beg;
    for (; e + 1 < end; e += 2) {
        int s0 = g_colsrc[e];
        int s1 = g_colsrc[e + 1];
        float4 a0 = *reinterpret_cast<const float4*>(g_alpha + (size_t)e * 4);
        float4 a1 = *reinterpret_cast<const float4*>(g_alpha + (size_t)(e + 1) * 4);
        const float* f0 = ft + (size_t)s0 * DIM;
        const float* f1 = ft + (size_t)s1 * DIM;
        float v00 = f0[lane], v01 = f0[32 + lane], v02 = f0[64 + lane], v03 = f0[96 + lane];
        float v10 = f1[lane], v11 = f1[32 + lane], v12 = f1[64 + lane], v13 = f1[96 + lane];
        acc0 += a0.x * v00 + a1.x * v10;
        acc1 += a0.y * v01 + a1.y * v11;
        acc2 += a0.z * v02 + a1.z * v12;
        acc3 += a0.w * v03 + a1.w * v13;
    }
    if (e < end) {
        int s = g_colsrc[e];
        float4 a = *reinterpret_cast<const float4*>(g_alpha + (size_t)e * 4);
        const float* f = ft + (size_t)s * DIM;
        acc0 += a.x * f[lane];
        acc1 += a.y * f[32 + lane];
        acc2 += a.z * f[64 + lane];
        acc3 += a.w * f[96 + lane];
    }

    float4 d = *reinterpret_cast<const float4*>(g_denom + i * 4);
    float v0 = acc0 / d.x + bias[lane];
    float v1 = acc1 / d.y + bias[32 + lane];
    float v2 = acc2 / d.z + bias[64 + lane];
    float v3 = acc3 / d.w + bias[96 + lane];

    if (!LAYER1) {
        out[(size_t)i * 128 + lane]      = fmaxf(v0, 0.f);
        out[(size_t)i * 128 + 32 + lane] = fmaxf(v1, 0.f);
        out[(size_t)i * 128 + 64 + lane] = fmaxf(v2, 0.f);
        out[(size_t)i * 128 + 96 + lane] = fmaxf(v3, 0.f);
    } else {
        out[(size_t)i * 32 + lane] = 0.25f * (v0 + v1 + v2 + v3);
    }
}

// ---------------- launch ----------------
extern "C" void kernel_launch(void* const* d_in, const int* in_sizes, int n_in,
                              void* d_out, int out_size) {
    const float *x_am, *x_ph, *exist, *am_exist;
    const int *src, *dst;
    const float *W0a, *al0a, *ar0a, *b0a, *W0p, *al0p, *ar0p, *b0p;
    const float *W1a, *al1a, *ar1a, *b1a, *W1p, *al1p, *ar1p, *b1p;

    x_am = (const float*)d_in[0];
    x_ph = (const float*)d_in[1];
    exist = (const float*)d_in[2];
    am_exist = (const float*)d_in[3];

    if (in_sizes[4] == N_EDGES) {
        src = (const int*)d_in[4];
        dst = (const int*)d_in[5];
        W0a = (const float*)d_in[6];  al0a = (const float*)d_in[7];
        ar0a = (const float*)d_in[8]; b0a = (const float*)d_in[9];
        W0p = (const float*)d_in[10]; al0p = (const float*)d_in[11];
        ar0p = (const float*)d_in[12]; b0p = (const float*)d_in[13];
        W1a = (const float*)d_in[14]; al1a = (const float*)d_in[15];
        ar1a = (const float*)d_in[16]; b1a = (const float*)d_in[17];
        W1p = (const float*)d_in[18]; al1p = (const float*)d_in[19];
        ar1p = (const float*)d_in[20]; b1p = (const float*)d_in[21];
    } else {
        W0a = (const float*)d_in[4];  al0a = (const float*)d_in[5];
        ar0a = (const float*)d_in[6]; b0a = (const float*)d_in[7];
        W0p = (const float*)d_in[8];  al0p = (const float*)d_in[9];
        ar0p = (const float*)d_in[10]; b0p = (const float*)d_in[11];
        W1a = (const float*)d_in[12]; al1a = (const float*)d_in[13];
        ar1a = (const float*)d_in[14]; b1a = (const float*)d_in[15];
        W1p = (const float*)d_in[16]; al1p = (const float*)d_in[17];
        ar1p = (const float*)d_in[18]; b1p = (const float*)d_in[19];
        src = (const int*)d_in[20];
        dst = (const int*)d_in[21];
    }

    float* out = (float*)d_out;

    float *p_ft, *p_h, *p_el, *p_er;
    cudaGetSymbolAddress((void**)&p_ft, g_ft);
    cudaGetSymbolAddress((void**)&p_h, g_h);
    cudaGetSymbolAddress((void**)&p_el, g_el);
    cudaGetSymbolAddress((void**)&p_er, g_er);

    const int TB = 256;
    int gb_nodes = (N_NODES + TB - 1) / TB;
    int gb_edges = (N_EDGES + TB - 1) / TB;
    int gb_warp_nodes = (N_NODES * 32 + TB - 1) / TB;

    // CSR build (shared by all 4 convs)
    zero_counts_kernel<<<gb_nodes, TB>>>();
    hist_kernel<<<gb_edges, TB>>>(dst);
    scan_partial_kernel<<<SCAN_NB, 256>>>();
    scan_bsum_kernel<<<1, 64>>>();
    scan_write_kernel<<<SCAN_NB, SCAN_B>>>();
    scatter_kernel<<<gb_edges, TB>>>(src, dst, am_exist, exist);

    int gemm_blocks = (N_NODES + 63) / 64;

    float *p_w_am, *p_w_ph;
    cudaGetSymbolAddress((void**)&p_w_am, g_w_am);
    cudaGetSymbolAddress((void**)&p_w_ph, g_w_ph);

    for (int br = 0; br < 2; br++) {
        const float* x  = br ? x_ph : x_am;
        const float* ew = br ? p_w_ph : p_w_am;
        const float* W0 = br ? W0p : W0a;
        const float* al0 = br ? al0p : al0a;
        const float* ar0 = br ? ar0p : ar0a;
        const float* b0 = br ? b0p : b0a;
        const float* W1 = br ? W1p : W1a;
        const float* al1 = br ? al1p : al1a;
        const float* ar1 = br ? ar1p : ar1a;
        const float* b1 = br ? b1p : b1a;
        float* out_br = out + (size_t)br * N_NODES * OUTF;

        // layer 0
        gemm128_kernel<<<gemm_blocks, 256>>>(x, W0, p_ft, N_NODES);
        elr_kernel<<<gb_warp_nodes, TB>>>(p_ft, al0, ar0, p_el, p_er);
        alpha_kernel<<<gb_warp_nodes, TB>>>(p_el, p_er, ew);
        aggregate_kernel<false><<<gb_warp_nodes, TB>>>(p_ft, b0, p_h);

        // layer 1
        gemm128_kernel<<<gemm_blocks, 256>>>(p_h, W1, p_ft, N_NODES);
        elr_kernel<<<gb_warp_nodes, TB>>>(p_ft, al1, ar1, p_el, p_er);
        alpha_kernel<<<gb_warp_nodes, TB>>>(p_el, p_er, ew);
        aggregate_kernel<true><<<gb_warp_nodes, TB>>>(p_ft, b1, out_br);
    }
}

// round 8
// speedup vs baseline: 2.4136x; 1.4266x over previous
#include <cuda_runtime.h>
#include <cuda_bf16.h>
#include <math.h>
#include <stdint.h>

#define N_NODES 50000
#define N_EDGES 800000
#define DIM 128
#define HEADS 4
#define OUTF 32
#define NEG_SLOPE 0.2f

#define SCAN_B 1024
#define SCAN_NB ((N_NODES + SCAN_B - 1) / SCAN_B)   // 49

// ---------------- scratch ----------------
__device__ int   g_counts[N_NODES];
__device__ int   g_rowptr[N_NODES + 1];
__device__ int   g_cursor[N_NODES];
__device__ int   g_colsrc[N_EDGES];
__device__ float g_w_am[N_EDGES];
__device__ float g_w_ph[N_EDGES];
__device__ float g_alpha[N_EDGES * HEADS];
__device__ float g_denom[N_NODES * HEADS];
__device__ float g_ft[N_NODES * DIM];
__device__ float g_h[N_NODES * DIM];
__device__ float g_el[N_NODES * HEADS];
__device__ float g_er[N_NODES * HEADS];
__device__ int   g_bsum[SCAN_NB];
__device__ int   g_bsumex[SCAN_NB];

__device__ __forceinline__ uint32_t tf32_rna(float x) {
    uint32_t r;
    asm("cvt.rna.tf32.f32 %0, %1;" : "=r"(r) : "f"(x));
    return r;
}

// ---------------- CSR build ----------------
__global__ void zero_counts_kernel() {
    int i = blockIdx.x * blockDim.x + threadIdx.x;
    if (i < N_NODES) g_counts[i] = 0;
}

__global__ void hist_kernel(const int* __restrict__ dst) {
    int e = blockIdx.x * blockDim.x + threadIdx.x;
    if (e < N_EDGES) atomicAdd(&g_counts[dst[e]], 1);
}

__global__ void scan_partial_kernel() {
    __shared__ int smem[256];
    int b = blockIdx.x, t = threadIdx.x;
    int base = b * SCAN_B;
    int s = 0;
    #pragma unroll
    for (int j = 0; j < 4; j++) {
        int i = base + t + j * 256;
        if (i < N_NODES) s += g_counts[i];
    }
    smem[t] = s;
    __syncthreads();
    for (int off = 128; off > 0; off >>= 1) {
        if (t < off) smem[t] += smem[t + off];
        __syncthreads();
    }
    if (t == 0) g_bsum[b] = smem[0];
}

__global__ void scan_bsum_kernel() {
    __shared__ int smem[64];
    int t = threadIdx.x;
    int v = (t < SCAN_NB) ? g_bsum[t] : 0;
    smem[t] = v;
    __syncthreads();
    #pragma unroll
    for (int off = 1; off < 64; off <<= 1) {
        int x = (t >= off) ? smem[t - off] : 0;
        __syncthreads();
        smem[t] += x;
        __syncthreads();
    }
    if (t < SCAN_NB) g_bsumex[t] = smem[t] - v;
}

__global__ void scan_write_kernel() {
    __shared__ int smem[SCAN_B];
    int b = blockIdx.x, t = threadIdx.x;
    int i = b * SCAN_B + t;
    int v = (i < N_NODES) ? g_counts[i] : 0;
    smem[t] = v;
    __syncthreads();
    #pragma unroll
    for (int off = 1; off < SCAN_B; off <<= 1) {
        int x = (t >= off) ? smem[t - off] : 0;
        __syncthreads();
        smem[t] += x;
        __syncthreads();
    }
    int excl = smem[t] - v + g_bsumex[b];
    if (i < N_NODES) {
        g_rowptr[i] = excl;
        g_cursor[i] = excl;
        if (i == N_NODES - 1) g_rowptr[N_NODES] = excl + v;
    }
}

__global__ void scatter_kernel(const int* __restrict__ src, const int* __restrict__ dst,
                               const float* __restrict__ am_w, const float* __restrict__ ph_w) {
    int e = blockIdx.x * blockDim.x + threadIdx.x;
    if (e >= N_EDGES) return;
    int d = dst[e];
    int pos = atomicAdd(&g_cursor[d], 1);
    g_colsrc[pos] = src[e];
    g_w_am[pos] = am_w[e];
    g_w_ph[pos] = ph_w[e];
}

// ---------------- tf32 mma.sync GEMM + fused el/er epilogue ----------------
// C[M x 128] = A[M x 128] * W[128 x 128]   (W row-major [k][n] = mma's col-major B)
// block: 256 threads (8 warps), 128 rows; warp w owns rows 16w..16w+15, all 128 cols.
#define A_STRIDE 132   // floats; 132 mod 32 = 4  -> a-frag LDS conflict-free
#define W_STRIDE 136   // floats; 136 mod 32 = 8  -> b-frag LDS conflict-free
#define GEMM_SMEM_FLOATS (128 * A_STRIDE + 128 * W_STRIDE + 256)
#define GEMM_SMEM_BYTES (GEMM_SMEM_FLOATS * 4)

__global__ void __launch_bounds__(256, 1) gemm_tf32_kernel(
    const float* __restrict__ A, const float* __restrict__ W,
    const float* __restrict__ al, const float* __restrict__ ar,
    float* __restrict__ C, float* __restrict__ el, float* __restrict__ er, int M)
{
    extern __shared__ float sm[];
    float* Asm = sm;                       // [128][A_STRIDE]
    float* Wsm = sm + 128 * A_STRIDE;      // [128][W_STRIDE]
    float* als = Wsm + 128 * W_STRIDE;     // [128]
    float* ars = als + 128;                // [128]

    int tid = threadIdx.x;
    int br = blockIdx.x * 128;

    // load A tile (convert to tf32 bit patterns)
    #pragma unroll
    for (int i = 0; i < 16; i++) {
        int idx = tid + i * 256;       // float4 units
        int row = idx >> 5;
        int c4 = (idx & 31) * 4;
        int gr = br + row;
        float4 v = make_float4(0.f, 0.f, 0.f, 0.f);
        if (gr < M) v = *reinterpret_cast<const float4*>(&A[(size_t)gr * 128 + c4]);
        float* p = &Asm[row * A_STRIDE + c4];
        p[0] = __uint_as_float(tf32_rna(v.x));
        p[1] = __uint_as_float(tf32_rna(v.y));
        p[2] = __uint_as_float(tf32_rna(v.z));
        p[3] = __uint_as_float(tf32_rna(v.w));
    }
    // load W tile
    #pragma unroll
    for (int i = 0; i < 16; i++) {
        int idx = tid + i * 256;
        int row = idx >> 5;
        int c4 = (idx & 31) * 4;
        float4 v = *reinterpret_cast<const float4*>(&W[(size_t)row * 128 + c4]);
        float* p = &Wsm[row * W_STRIDE + c4];
        p[0] = __uint_as_float(tf32_rna(v.x));
        p[1] = __uint_as_float(tf32_rna(v.y));
        p[2] = __uint_as_float(tf32_rna(v.z));
        p[3] = __uint_as_float(tf32_rna(v.w));
    }
    if (tid < 32) {
        *reinterpret_cast<float4*>(&als[tid * 4]) = *reinterpret_cast<const float4*>(&al[tid * 4]);
        *reinterpret_cast<float4*>(&ars[tid * 4]) = *reinterpret_cast<const float4*>(&ar[tid * 4]);
    }
    __syncthreads();

    int w = tid >> 5;
    int lane = tid & 31;
    int g = lane >> 2;     // groupID
    int q = lane & 3;      // threadID_in_group
    int lrow0 = w * 16 + g;
    int lrow1 = lrow0 + 8;

    float acc[16][4];
    #pragma unroll
    for (int j = 0; j < 16; j++) {
        acc[j][0] = 0.f; acc[j][1] = 0.f; acc[j][2] = 0.f; acc[j][3] = 0.f;
    }

    #pragma unroll
    for (int kk = 0; kk < 16; kk++) {
        int k0 = kk * 8;
        uint32_t a0 = __float_as_uint(Asm[lrow0 * A_STRIDE + k0 + q]);
        uint32_t a1 = __float_as_uint(Asm[lrow1 * A_STRIDE + k0 + q]);
        uint32_t a2 = __float_as_uint(Asm[lrow0 * A_STRIDE + k0 + q + 4]);
        uint32_t a3 = __float_as_uint(Asm[lrow1 * A_STRIDE + k0 + q + 4]);
        #pragma unroll
        for (int j = 0; j < 16; j++) {
            uint32_t b0 = __float_as_uint(Wsm[(k0 + q) * W_STRIDE + 8 * j + g]);
            uint32_t b1 = __float_as_uint(Wsm[(k0 + q + 4) * W_STRIDE + 8 * j + g]);
            asm volatile(
                "mma.sync.aligned.m16n8k8.row.col.f32.tf32.tf32.f32 "
                "{%0,%1,%2,%3}, {%4,%5,%6,%7}, {%8,%9}, {%0,%1,%2,%3};"
                : "+f"(acc[j][0]), "+f"(acc[j][1]), "+f"(acc[j][2]), "+f"(acc[j][3])
                : "r"(a0), "r"(a1), "r"(a2), "r"(a3), "r"(b0), "r"(b1));
        }
    }

    // epilogue: C store + fused el/er
    int grow0 = br + lrow0;
    int grow1 = br + lrow1;

    float el0[4] = {0.f, 0.f, 0.f, 0.f}, er0[4] = {0.f, 0.f, 0.f, 0.f};
    float el1[4] = {0.f, 0.f, 0.f, 0.f}, er1[4] = {0.f, 0.f, 0.f, 0.f};

    #pragma unroll
    for (int j = 0; j < 16; j++) {
        int c = 8 * j + 2 * q;
        int h = j >> 2;
        float w0 = als[c], w1 = als[c + 1];
        float r0 = ars[c], r1 = ars[c + 1];
        el0[h] += acc[j][0] * w0 + acc[j][1] * w1;
        er0[h] += acc[j][0] * r0 + acc[j][1] * r1;
        el1[h] += acc[j][2] * w0 + acc[j][3] * w1;
        er1[h] += acc[j][2] * r0 + acc[j][3] * r1;
        if (grow0 < M)
            *reinterpret_cast<float2*>(&C[(size_t)grow0 * 128 + c]) = make_float2(acc[j][0], acc[j][1]);
        if (grow1 < M)
            *reinterpret_cast<float2*>(&C[(size_t)grow1 * 128 + c]) = make_float2(acc[j][2], acc[j][3]);
    }

    // reduce across the quad (lanes sharing the same rows)
    #pragma unroll
    for (int h = 0; h < 4; h++) {
        #pragma unroll
        for (int off = 1; off < 4; off <<= 1) {
            el0[h] += __shfl_xor_sync(0xffffffffu, el0[h], off);
            er0[h] += __shfl_xor_sync(0xffffffffu, er0[h], off);
            el1[h] += __shfl_xor_sync(0xffffffffu, el1[h], off);
            er1[h] += __shfl_xor_sync(0xffffffffu, er1[h], off);
        }
    }
    if (q == 0) {
        if (grow0 < M) {
            *reinterpret_cast<float4*>(&el[grow0 * 4]) = make_float4(el0[0], el0[1], el0[2], el0[3]);
            *reinterpret_cast<float4*>(&er[grow0 * 4]) = make_float4(er0[0], er0[1], er0[2], er0[3]);
        }
        if (grow1 < M) {
            *reinterpret_cast<float4*>(&el[grow1 * 4]) = make_float4(el1[0], el1[1], el1[2], el1[3]);
            *reinterpret_cast<float4*>(&er[grow1 * 4]) = make_float4(er1[0], er1[1], er1[2], er1[3]);
        }
    }
}

// ---------------- leaky ----------------
__device__ __forceinline__ float leaky(float v) {
    return v > 0.f ? v : NEG_SLOPE * v;
}

// ---------------- alpha: single pass, no max shift (exp can't overflow here) ----------------
__global__ void alpha_kernel(const float* __restrict__ el, const float* __restrict__ er,
                             const float* __restrict__ w) {
    int i = (blockIdx.x * blockDim.x + threadIdx.x) >> 5;
    int lane = threadIdx.x & 31;
    if (i >= N_NODES) return;
    int beg = g_rowptr[i], end = g_rowptr[i + 1];
    float4 e4 = *reinterpret_cast<const float4*>(er + i * 4);

    float d0 = 0.f, d1 = 0.f, d2 = 0.f, d3 = 0.f;
    for (int e = beg + lane; e < end; e += 32) {
        int s = g_colsrc[e];
        float we = w[e];
        float4 lv = *reinterpret_cast<const float4*>(el + s * 4);
        float x0 = __expf(leaky(lv.x + e4.x));
        float x1 = __expf(leaky(lv.y + e4.y));
        float x2 = __expf(leaky(lv.z + e4.z));
        float x3 = __expf(leaky(lv.w + e4.w));
        d0 += x0; d1 += x1; d2 += x2; d3 += x3;
        float4 av = make_float4(x0 * we, x1 * we, x2 * we, x3 * we);
        *reinterpret_cast<float4*>(g_alpha + (size_t)e * 4) = av;
    }
    #pragma unroll
    for (int off = 16; off > 0; off >>= 1) {
        d0 += __shfl_xor_sync(0xffffffffu, d0, off);
        d1 += __shfl_xor_sync(0xffffffffu, d1, off);
        d2 += __shfl_xor_sync(0xffffffffu, d2, off);
        d3 += __shfl_xor_sync(0xffffffffu, d3, off);
    }
    if (lane == 0) {
        float4 dv = make_float4(fmaxf(d0, 1e-9f), fmaxf(d1, 1e-9f),
                                fmaxf(d2, 1e-9f), fmaxf(d3, 1e-9f));
        *reinterpret_cast<float4*>(g_denom + i * 4) = dv;
    }
}

// ---------------- aggregation: warp per node, lane = feature ----------------
template <bool LAYER1>
__global__ void aggregate_kernel(const float* __restrict__ ft,
                                 const float* __restrict__ bias,
                                 float* __restrict__ out) {
    int i = (blockIdx.x * blockDim.x + threadIdx.x) >> 5;
    int lane = threadIdx.x & 31;
    if (i >= N_NODES) return;
    int beg = g_rowptr[i], end = g_rowptr[i + 1];

    float acc0 = 0.f, acc1 = 0.f, acc2 = 0.f, acc3 = 0.f;
    int e = beg;
    for (; e + 1 < end; e += 2) {
        int s0 = g_colsrc[e];
        int s1 = g_colsrc[e + 1];
        float4 a0 = *reinterpret_cast<const float4*>(g_alpha + (size_t)e * 4);
        float4 a1 = *reinterpret_cast<const float4*>(g_alpha + (size_t)(e + 1) * 4);
        const float* f0 = ft + (size_t)s0 * DIM;
        const float* f1 = ft + (size_t)s1 * DIM;
        float v00 = f0[lane], v01 = f0[32 + lane], v02 = f0[64 + lane], v03 = f0[96 + lane];
        float v10 = f1[lane], v11 = f1[32 + lane], v12 = f1[64 + lane], v13 = f1[96 + lane];
        acc0 += a0.x * v00 + a1.x * v10;
        acc1 += a0.y * v01 + a1.y * v11;
        acc2 += a0.z * v02 + a1.z * v12;
        acc3 += a0.w * v03 + a1.w * v13;
    }
    if (e < end) {
        int s = g_colsrc[e];
        float4 a = *reinterpret_cast<const float4*>(g_alpha + (size_t)e * 4);
        const float* f = ft + (size_t)s * DIM;
        acc0 += a.x * f[lane];
        acc1 += a.y * f[32 + lane];
        acc2 += a.z * f[64 + lane];
        acc3 += a.w * f[96 + lane];
    }

    float4 dd = *reinterpret_cast<const float4*>(g_denom + i * 4);
    float v0 = acc0 / dd.x + bias[lane];
    float v1 = acc1 / dd.y + bias[32 + lane];
    float v2 = acc2 / dd.z + bias[64 + lane];
    float v3 = acc3 / dd.w + bias[96 + lane];

    if (!LAYER1) {
        out[(size_t)i * 128 + lane]      = fmaxf(v0, 0.f);
        out[(size_t)i * 128 + 32 + lane] = fmaxf(v1, 0.f);
        out[(size_t)i * 128 + 64 + lane] = fmaxf(v2, 0.f);
        out[(size_t)i * 128 + 96 + lane] = fmaxf(v3, 0.f);
    } else {
        out[(size_t)i * 32 + lane] = 0.25f * (v0 + v1 + v2 + v3);
    }
}

// ---------------- launch ----------------
extern "C" void kernel_launch(void* const* d_in, const int* in_sizes, int n_in,
                              void* d_out, int out_size) {
    const float *x_am, *x_ph, *exist, *am_exist;
    const int *src, *dst;
    const float *W0a, *al0a, *ar0a, *b0a, *W0p, *al0p, *ar0p, *b0p;
    const float *W1a, *al1a, *ar1a, *b1a, *W1p, *al1p, *ar1p, *b1p;

    x_am = (const float*)d_in[0];
    x_ph = (const float*)d_in[1];
    exist = (const float*)d_in[2];
    am_exist = (const float*)d_in[3];

    if (in_sizes[4] == N_EDGES) {
        src = (const int*)d_in[4];
        dst = (const int*)d_in[5];
        W0a = (const float*)d_in[6];  al0a = (const float*)d_in[7];
        ar0a = (const float*)d_in[8]; b0a = (const float*)d_in[9];
        W0p = (const float*)d_in[10]; al0p = (const float*)d_in[11];
        ar0p = (const float*)d_in[12]; b0p = (const float*)d_in[13];
        W1a = (const float*)d_in[14]; al1a = (const float*)d_in[15];
        ar1a = (const float*)d_in[16]; b1a = (const float*)d_in[17];
        W1p = (const float*)d_in[18]; al1p = (const float*)d_in[19];
        ar1p = (const float*)d_in[20]; b1p = (const float*)d_in[21];
    } else {
        W0a = (const float*)d_in[4];  al0a = (const float*)d_in[5];
        ar0a = (const float*)d_in[6]; b0a = (const float*)d_in[7];
        W0p = (const float*)d_in[8];  al0p = (const float*)d_in[9];
        ar0p = (const float*)d_in[10]; b0p = (const float*)d_in[11];
        W1a = (const float*)d_in[12]; al1a = (const float*)d_in[13];
        ar1a = (const float*)d_in[14]; b1a = (const float*)d_in[15];
        W1p = (const float*)d_in[16]; al1p = (const float*)d_in[17];
        ar1p = (const float*)d_in[18]; b1p = (const float*)d_in[19];
        src = (const int*)d_in[20];
        dst = (const int*)d_in[21];
    }

    float* out = (float*)d_out;

    float *p_ft, *p_h, *p_el, *p_er, *p_w_am, *p_w_ph;
    cudaGetSymbolAddress((void**)&p_ft, g_ft);
    cudaGetSymbolAddress((void**)&p_h, g_h);
    cudaGetSymbolAddress((void**)&p_el, g_el);
    cudaGetSymbolAddress((void**)&p_er, g_er);
    cudaGetSymbolAddress((void**)&p_w_am, g_w_am);
    cudaGetSymbolAddress((void**)&p_w_ph, g_w_ph);

    cudaFuncSetAttribute(gemm_tf32_kernel, cudaFuncAttributeMaxDynamicSharedMemorySize, GEMM_SMEM_BYTES);

    const int TB = 256;
    int gb_nodes = (N_NODES + TB - 1) / TB;
    int gb_edges = (N_EDGES + TB - 1) / TB;
    int gb_warp_nodes = (N_NODES * 32 + TB - 1) / TB;
    int gemm_blocks = (N_NODES + 127) / 128;

    // CSR build (shared by all 4 convs)
    zero_counts_kernel<<<gb_nodes, TB>>>();
    hist_kernel<<<gb_edges, TB>>>(dst);
    scan_partial_kernel<<<SCAN_NB, 256>>>();
    scan_bsum_kernel<<<1, 64>>>();
    scan_write_kernel<<<SCAN_NB, SCAN_B>>>();
    scatter_kernel<<<gb_edges, TB>>>(src, dst, am_exist, exist);

    for (int br = 0; br < 2; br++) {
        const float* x  = br ? x_ph : x_am;
        const float* ew = br ? p_w_ph : p_w_am;
        const float* W0 = br ? W0p : W0a;
        const float* al0 = br ? al0p : al0a;
        const float* ar0 = br ? ar0p : ar0a;
        const float* b0 = br ? b0p : b0a;
        const float* W1 = br ? W1p : W1a;
        const float* al1 = br ? al1p : al1a;
        const float* ar1 = br ? ar1p : ar1a;
        const float* b1 = br ? b1p : b1a;
        float* out_br = out + (size_t)br * N_NODES * OUTF;

        // layer 0
        gemm_tf32_kernel<<<gemm_blocks, 256, GEMM_SMEM_BYTES>>>(x, W0, al0, ar0, p_ft, p_el, p_er, N_NODES);
        alpha_kernel<<<gb_warp_nodes, TB>>>(p_el, p_er, ew);
        aggregate_kernel<false><<<gb_warp_nodes, TB>>>(p_ft, b0, p_h);

        // layer 1
        gemm_tf32_kernel<<<gemm_blocks, 256, GEMM_SMEM_BYTES>>>(p_h, W1, al1, ar1, p_ft, p_el, p_er, N_NODES);
        alpha_kernel<<<gb_warp_nodes, TB>>>(p_el, p_er, ew);
        aggregate_kernel<true><<<gb_warp_nodes, TB>>>(p_ft, b1, out_br);
    }
}

// round 9
// speedup vs baseline: 2.4557x; 1.0174x over previous
#include <cuda_runtime.h>
#include <cuda_bf16.h>
#include <math.h>
#include <stdint.h>

#define N_NODES 50000
#define N_EDGES 800000
#define DIM 128
#define HEADS 4
#define OUTF 32
#define NEG_SLOPE 0.2f

#define SCAN_B 1024
#define SCAN_NB ((N_NODES + SCAN_B - 1) / SCAN_B)   // 49

// ---------------- scratch ----------------
__device__ int   g_counts[N_NODES];
__device__ int   g_rowptr[N_NODES + 1];
__device__ int   g_cursor[N_NODES];
__device__ int   g_colsrc[N_EDGES];
__device__ float g_w_am[N_EDGES];
__device__ float g_w_ph[N_EDGES];
__device__ float g_ft[N_NODES * DIM];
__device__ float g_h[N_NODES * DIM];
__device__ float g_el[N_NODES * HEADS];
__device__ float g_er[N_NODES * HEADS];
__device__ int   g_bsum[SCAN_NB];
__device__ int   g_bsumex[SCAN_NB];

__device__ __forceinline__ uint32_t tf32_rna(float x) {
    uint32_t r;
    asm("cvt.rna.tf32.f32 %0, %1;" : "=r"(r) : "f"(x));
    return r;
}

// ---------------- CSR build ----------------
__global__ void zero_counts_kernel() {
    int i = blockIdx.x * blockDim.x + threadIdx.x;
    if (i < N_NODES) g_counts[i] = 0;
}

__global__ void hist_kernel(const int* __restrict__ dst) {
    int e = blockIdx.x * blockDim.x + threadIdx.x;
    if (e < N_EDGES) atomicAdd(&g_counts[dst[e]], 1);
}

__global__ void scan_partial_kernel() {
    __shared__ int smem[256];
    int b = blockIdx.x, t = threadIdx.x;
    int base = b * SCAN_B;
    int s = 0;
    #pragma unroll
    for (int j = 0; j < 4; j++) {
        int i = base + t + j * 256;
        if (i < N_NODES) s += g_counts[i];
    }
    smem[t] = s;
    __syncthreads();
    for (int off = 128; off > 0; off >>= 1) {
        if (t < off) smem[t] += smem[t + off];
        __syncthreads();
    }
    if (t == 0) g_bsum[b] = smem[0];
}

__global__ void scan_bsum_kernel() {
    __shared__ int smem[64];
    int t = threadIdx.x;
    int v = (t < SCAN_NB) ? g_bsum[t] : 0;
    smem[t] = v;
    __syncthreads();
    #pragma unroll
    for (int off = 1; off < 64; off <<= 1) {
        int x = (t >= off) ? smem[t - off] : 0;
        __syncthreads();
        smem[t] += x;
        __syncthreads();
    }
    if (t < SCAN_NB) g_bsumex[t] = smem[t] - v;
}

__global__ void scan_write_kernel() {
    __shared__ int smem[SCAN_B];
    int b = blockIdx.x, t = threadIdx.x;
    int i = b * SCAN_B + t;
    int v = (i < N_NODES) ? g_counts[i] : 0;
    smem[t] = v;
    __syncthreads();
    #pragma unroll
    for (int off = 1; off < SCAN_B; off <<= 1) {
        int x = (t >= off) ? smem[t - off] : 0;
        __syncthreads();
        smem[t] += x;
        __syncthreads();
    }
    int excl = smem[t] - v + g_bsumex[b];
    if (i < N_NODES) {
        g_rowptr[i] = excl;
        g_cursor[i] = excl;
        if (i == N_NODES - 1) g_rowptr[N_NODES] = excl + v;
    }
}

__global__ void scatter_kernel(const int* __restrict__ src, const int* __restrict__ dst,
                               const float* __restrict__ am_w, const float* __restrict__ ph_w) {
    int e = blockIdx.x * blockDim.x + threadIdx.x;
    if (e >= N_EDGES) return;
    int d = dst[e];
    int pos = atomicAdd(&g_cursor[d], 1);
    g_colsrc[pos] = src[e];
    g_w_am[pos] = am_w[e];
    g_w_ph[pos] = ph_w[e];
}

// ---------------- tf32 mma.sync GEMM + fused el/er epilogue ----------------
#define A_STRIDE 132
#define W_STRIDE 136
#define GEMM_SMEM_FLOATS (128 * A_STRIDE + 128 * W_STRIDE + 256)
#define GEMM_SMEM_BYTES (GEMM_SMEM_FLOATS * 4)

__global__ void __launch_bounds__(256, 1) gemm_tf32_kernel(
    const float* __restrict__ A, const float* __restrict__ W,
    const float* __restrict__ al, const float* __restrict__ ar,
    float* __restrict__ C, float* __restrict__ el, float* __restrict__ er, int M)
{
    extern __shared__ float sm[];
    float* Asm = sm;
    float* Wsm = sm + 128 * A_STRIDE;
    float* als = Wsm + 128 * W_STRIDE;
    float* ars = als + 128;

    int tid = threadIdx.x;
    int br = blockIdx.x * 128;

    #pragma unroll
    for (int i = 0; i < 16; i++) {
        int idx = tid + i * 256;
        int row = idx >> 5;
        int c4 = (idx & 31) * 4;
        int gr = br + row;
        float4 v = make_float4(0.f, 0.f, 0.f, 0.f);
        if (gr < M) v = *reinterpret_cast<const float4*>(&A[(size_t)gr * 128 + c4]);
        float* p = &Asm[row * A_STRIDE + c4];
        p[0] = __uint_as_float(tf32_rna(v.x));
        p[1] = __uint_as_float(tf32_rna(v.y));
        p[2] = __uint_as_float(tf32_rna(v.z));
        p[3] = __uint_as_float(tf32_rna(v.w));
    }
    #pragma unroll
    for (int i = 0; i < 16; i++) {
        int idx = tid + i * 256;
        int row = idx >> 5;
        int c4 = (idx & 31) * 4;
        float4 v = *reinterpret_cast<const float4*>(&W[(size_t)row * 128 + c4]);
        float* p = &Wsm[row * W_STRIDE + c4];
        p[0] = __uint_as_float(tf32_rna(v.x));
        p[1] = __uint_as_float(tf32_rna(v.y));
        p[2] = __uint_as_float(tf32_rna(v.z));
        p[3] = __uint_as_float(tf32_rna(v.w));
    }
    if (tid < 32) {
        *reinterpret_cast<float4*>(&als[tid * 4]) = *reinterpret_cast<const float4*>(&al[tid * 4]);
        *reinterpret_cast<float4*>(&ars[tid * 4]) = *reinterpret_cast<const float4*>(&ar[tid * 4]);
    }
    __syncthreads();

    int w = tid >> 5;
    int lane = tid & 31;
    int g = lane >> 2;
    int q = lane & 3;
    int lrow0 = w * 16 + g;
    int lrow1 = lrow0 + 8;

    float acc[16][4];
    #pragma unroll
    for (int j = 0; j < 16; j++) {
        acc[j][0] = 0.f; acc[j][1] = 0.f; acc[j][2] = 0.f; acc[j][3] = 0.f;
    }

    #pragma unroll
    for (int kk = 0; kk < 16; kk++) {
        int k0 = kk * 8;
        uint32_t a0 = __float_as_uint(Asm[lrow0 * A_STRIDE + k0 + q]);
        uint32_t a1 = __float_as_uint(Asm[lrow1 * A_STRIDE + k0 + q]);
        uint32_t a2 = __float_as_uint(Asm[lrow0 * A_STRIDE + k0 + q + 4]);
        uint32_t a3 = __float_as_uint(Asm[lrow1 * A_STRIDE + k0 + q + 4]);
        #pragma unroll
        for (int j = 0; j < 16; j++) {
            uint32_t b0 = __float_as_uint(Wsm[(k0 + q) * W_STRIDE + 8 * j + g]);
            uint32_t b1 = __float_as_uint(Wsm[(k0 + q + 4) * W_STRIDE + 8 * j + g]);
            asm volatile(
                "mma.sync.aligned.m16n8k8.row.col.f32.tf32.tf32.f32 "
                "{%0,%1,%2,%3}, {%4,%5,%6,%7}, {%8,%9}, {%0,%1,%2,%3};"
                : "+f"(acc[j][0]), "+f"(acc[j][1]), "+f"(acc[j][2]), "+f"(acc[j][3])
                : "r"(a0), "r"(a1), "r"(a2), "r"(a3), "r"(b0), "r"(b1));
        }
    }

    int grow0 = br + lrow0;
    int grow1 = br + lrow1;

    float el0[4] = {0.f, 0.f, 0.f, 0.f}, er0[4] = {0.f, 0.f, 0.f, 0.f};
    float el1[4] = {0.f, 0.f, 0.f, 0.f}, er1[4] = {0.f, 0.f, 0.f, 0.f};

    #pragma unroll
    for (int j = 0; j < 16; j++) {
        int c = 8 * j + 2 * q;
        int h = j >> 2;
        float w0 = als[c], w1 = als[c + 1];
        float r0 = ars[c], r1 = ars[c + 1];
        el0[h] += acc[j][0] * w0 + acc[j][1] * w1;
        er0[h] += acc[j][0] * r0 + acc[j][1] * r1;
        el1[h] += acc[j][2] * w0 + acc[j][3] * w1;
        er1[h] += acc[j][2] * r0 + acc[j][3] * r1;
        if (grow0 < M)
            *reinterpret_cast<float2*>(&C[(size_t)grow0 * 128 + c]) = make_float2(acc[j][0], acc[j][1]);
        if (grow1 < M)
            *reinterpret_cast<float2*>(&C[(size_t)grow1 * 128 + c]) = make_float2(acc[j][2], acc[j][3]);
    }

    #pragma unroll
    for (int h = 0; h < 4; h++) {
        #pragma unroll
        for (int off = 1; off < 4; off <<= 1) {
            el0[h] += __shfl_xor_sync(0xffffffffu, el0[h], off);
            er0[h] += __shfl_xor_sync(0xffffffffu, er0[h], off);
            el1[h] += __shfl_xor_sync(0xffffffffu, el1[h], off);
            er1[h] += __shfl_xor_sync(0xffffffffu, er1[h], off);
        }
    }
    if (q == 0) {
        if (grow0 < M) {
            *reinterpret_cast<float4*>(&el[grow0 * 4]) = make_float4(el0[0], el0[1], el0[2], el0[3]);
            *reinterpret_cast<float4*>(&er[grow0 * 4]) = make_float4(er0[0], er0[1], er0[2], er0[3]);
        }
        if (grow1 < M) {
            *reinterpret_cast<float4*>(&el[grow1 * 4]) = make_float4(el1[0], el1[1], el1[2], el1[3]);
            *reinterpret_cast<float4*>(&er[grow1 * 4]) = make_float4(er1[0], er1[1], er1[2], er1[3]);
        }
    }
}

// ---------------- leaky ----------------
__device__ __forceinline__ float leaky(float v) {
    return v > 0.f ? v : NEG_SLOPE * v;
}

// ---------------- fused softmax + aggregation: warp per node ----------------
// Phase A (per 32-edge chunk): lane-parallel alpha compute (exp + weight).
// Phase B: serial edge loop with shfl-broadcast alpha, lane = feature.
template <bool LAYER1>
__global__ void fused_agg_kernel(const float* __restrict__ ft,
                                 const float* __restrict__ el, const float* __restrict__ er,
                                 const float* __restrict__ w,
                                 const float* __restrict__ bias,
                                 float* __restrict__ out) {
    int i = (blockIdx.x * blockDim.x + threadIdx.x) >> 5;
    int lane = threadIdx.x & 31;
    if (i >= N_NODES) return;
    int beg = g_rowptr[i], end = g_rowptr[i + 1];
    float4 e4 = *reinterpret_cast<const float4*>(er + i * 4);

    float acc0 = 0.f, acc1 = 0.f, acc2 = 0.f, acc3 = 0.f;
    float d0 = 0.f, d1 = 0.f, d2 = 0.f, d3 = 0.f;

    for (int chunk = beg; chunk < end; chunk += 32) {
        int n = end - chunk;
        if (n > 32) n = 32;

        // phase A: lane-parallel alpha
        int s = 0;
        float xw0 = 0.f, xw1 = 0.f, xw2 = 0.f, xw3 = 0.f;
        if (lane < n) {
            int e = chunk + lane;
            s = g_colsrc[e];
            float we = w[e];
            float4 lv = *reinterpret_cast<const float4*>(el + s * 4);
            float x0 = __expf(leaky(lv.x + e4.x));
            float x1 = __expf(leaky(lv.y + e4.y));
            float x2 = __expf(leaky(lv.z + e4.z));
            float x3 = __expf(leaky(lv.w + e4.w));
            d0 += x0; d1 += x1; d2 += x2; d3 += x3;
            xw0 = x0 * we; xw1 = x1 * we; xw2 = x2 * we; xw3 = x3 * we;
        }

        // phase B: broadcast + gather, 2-way unrolled
        int j = 0;
        for (; j + 1 < n; j += 2) {
            int sA = __shfl_sync(0xffffffffu, s, j);
            int sB = __shfl_sync(0xffffffffu, s, j + 1);
            float aA0 = __shfl_sync(0xffffffffu, xw0, j);
            float aA1 = __shfl_sync(0xffffffffu, xw1, j);
            float aA2 = __shfl_sync(0xffffffffu, xw2, j);
            float aA3 = __shfl_sync(0xffffffffu, xw3, j);
            float aB0 = __shfl_sync(0xffffffffu, xw0, j + 1);
            float aB1 = __shfl_sync(0xffffffffu, xw1, j + 1);
            float aB2 = __shfl_sync(0xffffffffu, xw2, j + 1);
            float aB3 = __shfl_sync(0xffffffffu, xw3, j + 1);
            const float* fA = ft + (size_t)sA * DIM;
            const float* fB = ft + (size_t)sB * DIM;
            float vA0 = fA[lane], vA1 = fA[32 + lane], vA2 = fA[64 + lane], vA3 = fA[96 + lane];
            float vB0 = fB[lane], vB1 = fB[32 + lane], vB2 = fB[64 + lane], vB3 = fB[96 + lane];
            acc0 += aA0 * vA0 + aB0 * vB0;
            acc1 += aA1 * vA1 + aB1 * vB1;
            acc2 += aA2 * vA2 + aB2 * vB2;
            acc3 += aA3 * vA3 + aB3 * vB3;
        }
        if (j < n) {
            int sA = __shfl_sync(0xffffffffu, s, j);
            float aA0 = __shfl_sync(0xffffffffu, xw0, j);
            float aA1 = __shfl_sync(0xffffffffu, xw1, j);
            float aA2 = __shfl_sync(0xffffffffu, xw2, j);
            float aA3 = __shfl_sync(0xffffffffu, xw3, j);
            const float* fA = ft + (size_t)sA * DIM;
            acc0 += aA0 * fA[lane];
            acc1 += aA1 * fA[32 + lane];
            acc2 += aA2 * fA[64 + lane];
            acc3 += aA3 * fA[96 + lane];
        }
    }

    // reduce denominators across lanes
    #pragma unroll
    for (int off = 16; off > 0; off >>= 1) {
        d0 += __shfl_xor_sync(0xffffffffu, d0, off);
        d1 += __shfl_xor_sync(0xffffffffu, d1, off);
        d2 += __shfl_xor_sync(0xffffffffu, d2, off);
        d3 += __shfl_xor_sync(0xffffffffu, d3, off);
    }
    d0 = fmaxf(d0, 1e-9f); d1 = fmaxf(d1, 1e-9f);
    d2 = fmaxf(d2, 1e-9f); d3 = fmaxf(d3, 1e-9f);

    float v0 = acc0 / d0 + bias[lane];
    float v1 = acc1 / d1 + bias[32 + lane];
    float v2 = acc2 / d2 + bias[64 + lane];
    float v3 = acc3 / d3 + bias[96 + lane];

    if (!LAYER1) {
        out[(size_t)i * 128 + lane]      = fmaxf(v0, 0.f);
        out[(size_t)i * 128 + 32 + lane] = fmaxf(v1, 0.f);
        out[(size_t)i * 128 + 64 + lane] = fmaxf(v2, 0.f);
        out[(size_t)i * 128 + 96 + lane] = fmaxf(v3, 0.f);
    } else {
        out[(size_t)i * 32 + lane] = 0.25f * (v0 + v1 + v2 + v3);
    }
}

// ---------------- launch ----------------
extern "C" void kernel_launch(void* const* d_in, const int* in_sizes, int n_in,
                              void* d_out, int out_size) {
    const float *x_am, *x_ph, *exist, *am_exist;
    const int *src, *dst;
    const float *W0a, *al0a, *ar0a, *b0a, *W0p, *al0p, *ar0p, *b0p;
    const float *W1a, *al1a, *ar1a, *b1a, *W1p, *al1p, *ar1p, *b1p;

    x_am = (const float*)d_in[0];
    x_ph = (const float*)d_in[1];
    exist = (const float*)d_in[2];
    am_exist = (const float*)d_in[3];

    if (in_sizes[4] == N_EDGES) {
        src = (const int*)d_in[4];
        dst = (const int*)d_in[5];
        W0a = (const float*)d_in[6];  al0a = (const float*)d_in[7];
        ar0a = (const float*)d_in[8]; b0a = (const float*)d_in[9];
        W0p = (const float*)d_in[10]; al0p = (const float*)d_in[11];
        ar0p = (const float*)d_in[12]; b0p = (const float*)d_in[13];
        W1a = (const float*)d_in[14]; al1a = (const float*)d_in[15];
        ar1a = (const float*)d_in[16]; b1a = (const float*)d_in[17];
        W1p = (const float*)d_in[18]; al1p = (const float*)d_in[19];
        ar1p = (const float*)d_in[20]; b1p = (const float*)d_in[21];
    } else {
        W0a = (const float*)d_in[4];  al0a = (const float*)d_in[5];
        ar0a = (const float*)d_in[6]; b0a = (const float*)d_in[7];
        W0p = (const float*)d_in[8];  al0p = (const float*)d_in[9];
        ar0p = (const float*)d_in[10]; b0p = (const float*)d_in[11];
        W1a = (const float*)d_in[12]; al1a = (const float*)d_in[13];
        ar1a = (const float*)d_in[14]; b1a = (const float*)d_in[15];
        W1p = (const float*)d_in[16]; al1p = (const float*)d_in[17];
        ar1p = (const float*)d_in[18]; b1p = (const float*)d_in[19];
        src = (const int*)d_in[20];
        dst = (const int*)d_in[21];
    }

    float* out = (float*)d_out;

    float *p_ft, *p_h, *p_el, *p_er, *p_w_am, *p_w_ph;
    cudaGetSymbolAddress((void**)&p_ft, g_ft);
    cudaGetSymbolAddress((void**)&p_h, g_h);
    cudaGetSymbolAddress((void**)&p_el, g_el);
    cudaGetSymbolAddress((void**)&p_er, g_er);
    cudaGetSymbolAddress((void**)&p_w_am, g_w_am);
    cudaGetSymbolAddress((void**)&p_w_ph, g_w_ph);

    cudaFuncSetAttribute(gemm_tf32_kernel, cudaFuncAttributeMaxDynamicSharedMemorySize, GEMM_SMEM_BYTES);

    const int TB = 256;
    int gb_nodes = (N_NODES + TB - 1) / TB;
    int gb_edges = (N_EDGES + TB - 1) / TB;
    int gb_warp_nodes = (N_NODES * 32 + TB - 1) / TB;
    int gemm_blocks = (N_NODES + 127) / 128;

    // CSR build (shared by all 4 convs)
    zero_counts_kernel<<<gb_nodes, TB>>>();
    hist_kernel<<<gb_edges, TB>>>(dst);
    scan_partial_kernel<<<SCAN_NB, 256>>>();
    scan_bsum_kernel<<<1, 64>>>();
    scan_write_kernel<<<SCAN_NB, SCAN_B>>>();
    scatter_kernel<<<gb_edges, TB>>>(src, dst, am_exist, exist);

    for (int br = 0; br < 2; br++) {
        const float* x  = br ? x_ph : x_am;
        const float* ew = br ? p_w_ph : p_w_am;
        const float* W0 = br ? W0p : W0a;
        const float* al0 = br ? al0p : al0a;
        const float* ar0 = br ? ar0p : ar0a;
        const float* b0 = br ? b0p : b0a;
        const float* W1 = br ? W1p : W1a;
        const float* al1 = br ? al1p : al1a;
        const float* ar1 = br ? ar1p : ar1a;
        const float* b1 = br ? b1p : b1a;
        float* out_br = out + (size_t)br * N_NODES * OUTF;

        // layer 0
        gemm_tf32_kernel<<<gemm_blocks, 256, GEMM_SMEM_BYTES>>>(x, W0, al0, ar0, p_ft, p_el, p_er, N_NODES);
        fused_agg_kernel<false><<<gb_warp_nodes, TB>>>(p_ft, p_el, p_er, ew, b0, p_h);

        // layer 1
        gemm_tf32_kernel<<<gemm_blocks, 256, GEMM_SMEM_BYTES>>>(p_h, W1, al1, ar1, p_ft, p_el, p_er, N_NODES);
        fused_agg_kernel<true><<<gb_warp_nodes, TB>>>(p_ft, p_el, p_er, ew, b1, out_br);
    }
}